// round 3
// baseline (speedup 1.0000x reference)
#include <cuda_runtime.h>

#define N 4096
#define K 512
#define KSEL 31   // n_nbg + 1

// ---- scratch (no allocations allowed) ----
__device__ float g_d2[(size_t)N * N];   // 64 MB pairwise squared distances
__device__ float g_sq[N];               // row norms
__device__ float g_t[N];                // 31st-smallest d2 per row (mask threshold)
__device__ float g_inv[N];              // 1 / denom (gaussian inverse scale)

// ============================================================
// Kernel 1: row squared norms. One block (128 threads) per row.
// ============================================================
__global__ void norms_kernel(const float* __restrict__ X) {
    int row = blockIdx.x;
    int t = threadIdx.x;                       // 0..127, K/4 = 128 float4
    const float4* x4 = reinterpret_cast<const float4*>(X + (size_t)row * K);
    float4 v = x4[t];
    float s = v.x * v.x + v.y * v.y + v.z * v.z + v.w * v.w;
    #pragma unroll
    for (int o = 16; o; o >>= 1) s += __shfl_xor_sync(0xffffffffu, s, o);
    __shared__ float ws[4];
    if ((t & 31) == 0) ws[t >> 5] = s;
    __syncthreads();
    if (t == 0) g_sq[row] = ws[0] + ws[1] + ws[2] + ws[3];
}

// ============================================================
// Kernel 2: d2 = max(sq_i + sq_j - 2*X·X^T, 0), symmetric.
// 128x128 output tile, BK=16, 256 threads, 8x8 microtile.
// Only upper-triangular block tiles computed; each writes its
// tile and the transposed tile.
// ============================================================
#define BM 128
#define BK 16
#define LDA (BM + 4)

__global__ void __launch_bounds__(256, 2) d2_kernel(const float* __restrict__ X) {
    const int by = blockIdx.y, bx = blockIdx.x;
    if (bx < by) return;                 // triangular: bx >= by

    __shared__ float As[BK][LDA];
    __shared__ float Bs[BK][LDA];

    const int t  = threadIdx.x;
    const int tx = t & 15;               // 0..15 -> 8 cols each
    const int ty = t >> 4;               // 0..15 -> 8 rows each
    const int i0 = by * BM;
    const int j0 = bx * BM;

    float acc[8][8];
    #pragma unroll
    for (int i = 0; i < 8; i++)
        #pragma unroll
        for (int j = 0; j < 8; j++) acc[i][j] = 0.f;

    for (int kk = 0; kk < K; kk += BK) {
        // load 128 rows x 16 k for A and B operands (512 float4 each)
        #pragma unroll
        for (int l = 0; l < 2; l++) {
            int v  = t + l * 256;        // 0..511
            int r  = v >> 2;
            int c4 = (v & 3) * 4;
            float4 a = *reinterpret_cast<const float4*>(X + (size_t)(i0 + r) * K + kk + c4);
            As[c4 + 0][r] = a.x; As[c4 + 1][r] = a.y;
            As[c4 + 2][r] = a.z; As[c4 + 3][r] = a.w;
            float4 b = *reinterpret_cast<const float4*>(X + (size_t)(j0 + r) * K + kk + c4);
            Bs[c4 + 0][r] = b.x; Bs[c4 + 1][r] = b.y;
            Bs[c4 + 2][r] = b.z; Bs[c4 + 3][r] = b.w;
        }
        __syncthreads();

        #pragma unroll
        for (int k = 0; k < BK; k++) {
            float a[8], b[8];
            #pragma unroll
            for (int i = 0; i < 8; i++) a[i] = As[k][ty * 8 + i];
            #pragma unroll
            for (int j = 0; j < 8; j++) b[j] = Bs[k][tx * 8 + j];
            #pragma unroll
            for (int i = 0; i < 8; i++)
                #pragma unroll
                for (int j = 0; j < 8; j++) acc[i][j] = fmaf(a[i], b[j], acc[i][j]);
        }
        __syncthreads();
    }

    // epilogue: d2 = max(sq_i + sq_j - 2*dot, 0); write tile + transpose
    float sqi[8], sqj[8];
    #pragma unroll
    for (int i = 0; i < 8; i++) sqi[i] = g_sq[i0 + ty * 8 + i];
    #pragma unroll
    for (int j = 0; j < 8; j++) sqj[j] = g_sq[j0 + tx * 8 + j];

    float d[8][8];
    #pragma unroll
    for (int i = 0; i < 8; i++)
        #pragma unroll
        for (int j = 0; j < 8; j++)
            d[i][j] = fmaxf(fmaf(-2.0f, acc[i][j], sqi[i] + sqj[j]), 0.0f);

    // normal tile: rows i0+ty*8+i, cols j0+tx*8 .. +7 (two float4 per row)
    #pragma unroll
    for (int i = 0; i < 8; i++) {
        float* p = g_d2 + (size_t)(i0 + ty * 8 + i) * N + j0 + tx * 8;
        *reinterpret_cast<float4*>(p)     = make_float4(d[i][0], d[i][1], d[i][2], d[i][3]);
        *reinterpret_cast<float4*>(p + 4) = make_float4(d[i][4], d[i][5], d[i][6], d[i][7]);
    }
    // transposed tile: rows j0+tx*8+j, cols i0+ty*8 .. +7
    #pragma unroll
    for (int j = 0; j < 8; j++) {
        float* p = g_d2 + (size_t)(j0 + tx * 8 + j) * N + i0 + ty * 8;
        *reinterpret_cast<float4*>(p)     = make_float4(d[0][j], d[1][j], d[2][j], d[3][j]);
        *reinterpret_cast<float4*>(p + 4) = make_float4(d[4][j], d[5][j], d[6][j], d[7][j]);
    }
}

// ============================================================
// Kernel 3: per-row exact 31st-smallest d2 via bitwise binary
// search on float bit patterns (all values >= 0 so uint order
// == float order). One block (256 threads) per row.
// Each bit-iteration gets its own shared counter slot -> no
// reset race between iterations (the Round-1 bug).
// ============================================================
__global__ void __launch_bounds__(256) select_kernel() {
    const int row = blockIdx.x;
    const int t = threadIdx.x;
    __shared__ unsigned su[N];           // 16 KB
    __shared__ int cnts[31];

    const float* drow = g_d2 + (size_t)row * N;
    for (int i = t; i < N; i += 256) su[i] = __float_as_uint(drow[i]);
    if (t < 31) cnts[t] = 0;
    __syncthreads();

    unsigned T = 0;
    for (int b = 30; b >= 0; b--) {
        const unsigned cand = T | (1u << b);
        const int slot = 30 - b;
        int c = 0;
        #pragma unroll 4
        for (int i = t; i < N; i += 256) c += (su[i] < cand);
        #pragma unroll
        for (int o = 16; o; o >>= 1) c += __shfl_xor_sync(0xffffffffu, c, o);
        if ((t & 31) == 0) atomicAdd(&cnts[slot], c);
        __syncthreads();                 // all atomics to cnts[slot] done
        if (cnts[slot] < KSEL) T = cand; // every thread reads same settled value;
                                         // next iteration uses a different slot
    }

    if (t == 0) {
        float tv = __uint_as_float(T);   // 31st smallest d2 (== scale^2 pre-clamp)
        g_t[row] = tv;
        float scale = sqrtf(fmaxf(tv, 1e-12f));
        float denom = fmaxf(scale, 1e-8f);
        denom *= denom;
        g_inv[row] = 1.0f / denom;
    }
}

// ============================================================
// Kernel 4: out[i][j] = 0.5*( [d<=t_i]*exp(-d*inv_i)
//                           + [d<=t_j]*exp(-d*inv_j) )
// One float4 per thread.
// ============================================================
__global__ void __launch_bounds__(256) out_kernel(float* __restrict__ outp) {
    size_t gid = (size_t)blockIdx.x * 256 + threadIdx.x;  // float4 index
    int row = (int)(gid >> 10);                           // N/4 = 1024 f4/row
    int c0  = (int)(gid & 1023) << 2;

    float ti   = g_t[row];
    float invi = g_inv[row];
    float4 d  = *reinterpret_cast<const float4*>(g_d2 + (size_t)row * N + c0);
    float4 tj = *reinterpret_cast<const float4*>(g_t + c0);
    float4 ij = *reinterpret_cast<const float4*>(g_inv + c0);

    float4 o;
    o.x = 0.5f * ((d.x <= ti ? __expf(-d.x * invi) : 0.f) + (d.x <= tj.x ? __expf(-d.x * ij.x) : 0.f));
    o.y = 0.5f * ((d.y <= ti ? __expf(-d.y * invi) : 0.f) + (d.y <= tj.y ? __expf(-d.y * ij.y) : 0.f));
    o.z = 0.5f * ((d.z <= ti ? __expf(-d.z * invi) : 0.f) + (d.z <= tj.z ? __expf(-d.z * ij.z) : 0.f));
    o.w = 0.5f * ((d.w <= ti ? __expf(-d.w * invi) : 0.f) + (d.w <= tj.w ? __expf(-d.w * ij.w) : 0.f));
    *reinterpret_cast<float4*>(outp + (size_t)row * N + c0) = o;
}

// ============================================================
extern "C" void kernel_launch(void* const* d_in, const int* in_sizes, int n_in,
                              void* d_out, int out_size) {
    const float* X = (const float*)d_in[0];
    float* outp = (float*)d_out;

    norms_kernel<<<N, 128>>>(X);

    dim3 grid2(N / BM, N / BM);          // triangular early-exit inside
    d2_kernel<<<grid2, 256>>>(X);

    select_kernel<<<N, 256>>>();

    out_kernel<<<(size_t)N * N / 4 / 256, 256>>>(outp);
}

// round 5
// speedup vs baseline: 1.4899x; 1.4899x over previous
#include <cuda_runtime.h>
#include <cstdint>

#define N 4096
#define K 512
#define KSEL 31

__device__ float g_d2[(size_t)N * N];
__device__ float g_sq[N];
__device__ float g_t[N];
__device__ float g_inv[N];
__device__ float g_Xhi[(size_t)N * K];
__device__ float g_Xlo[(size_t)N * K];

__device__ __forceinline__ uint32_t smem_u32(const void* p) {
    uint32_t a;
    asm("{ .reg .u64 t; cvta.to.shared.u64 t, %1; cvt.u32.u64 %0, t; }" : "=r"(a) : "l"(p));
    return a;
}
#define CP_COMMIT() asm volatile("cp.async.commit_group;" ::: "memory")
#define CP_WAIT(n)  asm volatile("cp.async.wait_group %0;" :: "n"(n) : "memory")

__device__ __forceinline__ void mma8(float* c, const uint32_t* a, const uint32_t* b) {
    asm("mma.sync.aligned.m16n8k8.row.col.f32.tf32.tf32.f32 "
        "{%0,%1,%2,%3}, {%4,%5,%6,%7}, {%8,%9}, {%0,%1,%2,%3};"
        : "+f"(c[0]), "+f"(c[1]), "+f"(c[2]), "+f"(c[3])
        : "r"(a[0]), "r"(a[1]), "r"(a[2]), "r"(a[3]), "r"(b[0]), "r"(b[1]));
}
// smem tile layout: [r][16] floats, group-of-4 xor swizzle -> conflict-free frags
__device__ __forceinline__ int adr(int r, int c) {
    return r * 16 + ((((c) >> 2) ^ ((r >> 1) & 3)) << 2) + (c & 3);
}
#define SWI(i) ((((i) >> 2) + (((i) & 3) << 3)) & 31)

// ---------------- convert: X -> tf32 hi + tf32 lo ----------------
__global__ void convert_kernel(const float* __restrict__ X) {
    size_t i = (size_t)blockIdx.x * 256 + threadIdx.x;
    float4 v = reinterpret_cast<const float4*>(X)[i];
    float4 h, l;
    uint32_t u;
    #define CVT(comp) \
        asm("cvt.rna.tf32.f32 %0, %1;" : "=r"(u) : "f"(v.comp)); h.comp = __uint_as_float(u); \
        { float lo = v.comp - h.comp; asm("cvt.rna.tf32.f32 %0, %1;" : "=r"(u) : "f"(lo)); l.comp = __uint_as_float(u); }
    CVT(x) CVT(y) CVT(z) CVT(w)
    #undef CVT
    reinterpret_cast<float4*>(g_Xhi)[i] = h;
    reinterpret_cast<float4*>(g_Xlo)[i] = l;
}

// ---------------- norms ----------------
__global__ void norms_kernel(const float* __restrict__ X) {
    int row = blockIdx.x, t = threadIdx.x;
    float4 v = reinterpret_cast<const float4*>(X + (size_t)row * K)[t];
    float s = v.x * v.x + v.y * v.y + v.z * v.z + v.w * v.w;
    #pragma unroll
    for (int o = 16; o; o >>= 1) s += __shfl_xor_sync(0xffffffffu, s, o);
    __shared__ float ws[4];
    if ((t & 31) == 0) ws[t >> 5] = s;
    __syncthreads();
    if (t == 0) g_sq[row] = ws[0] + ws[1] + ws[2] + ws[3];
}

// ---------------- GEMM via mma.sync tf32 (3-term split) ----------------
// stage = 4 bufs (Ahi,Alo,Bhi,Blo) x 128x16 floats = 8192 floats = 32KB
__device__ __forceinline__ void cp_stage(float* sm, int s, int kc, int tid, int i0, int j0) {
    float* base = sm + s * 8192;
    #pragma unroll
    for (int q = 0; q < 8; q++) {
        int idx = tid + 256 * q;
        int buf = idx >> 9, r = (idx >> 2) & 127, g = idx & 3;
        const float* src = ((buf & 1) ? g_Xlo : g_Xhi)
                         + (size_t)(((buf < 2) ? i0 : j0) + r) * K + kc * 16 + g * 4;
        uint32_t dst = smem_u32(base + buf * 2048 + r * 16 + ((g ^ ((r >> 1) & 3)) << 2));
        asm volatile("cp.async.cg.shared.global [%0], [%1], 16;" :: "r"(dst), "l"(src));
    }
}

__global__ void __launch_bounds__(256, 2) gemm_kernel() {
    __shared__ float s_sqi[128], s_sqj[128];
    extern __shared__ float sm[];        // 16384 floats: 2 stages; epi aliases

    int t = blockIdx.x;                  // triangular tile id -> (by,bx), bx>=by
    int by = (int)(32.5f - sqrtf(32.5f * 32.5f - 2.0f * (float)t));
    while (by * (65 - by) / 2 > t) by--;
    while ((by + 1) * (64 - by) / 2 <= t) by++;
    int bx = by + (t - by * (65 - by) / 2);
    const int i0 = by * 128, j0 = bx * 128;

    const int tid = threadIdx.x;
    const int warp = tid >> 5, lane = tid & 31;
    const int wm = warp & 1, wn = warp >> 1;
    const int l4 = lane >> 2, lm = lane & 3;

    if (tid < 128) { s_sqi[tid] = g_sq[i0 + tid]; s_sqj[tid] = g_sq[j0 + tid]; }

    float acc[4][4][4];
    #pragma unroll
    for (int a = 0; a < 4; a++)
        #pragma unroll
        for (int b = 0; b < 4; b++)
            #pragma unroll
            for (int c = 0; c < 4; c++) acc[a][b][c] = 0.f;

    cp_stage(sm, 0, 0, tid, i0, j0);
    CP_COMMIT();

    for (int it = 0; it < 32; it++) {
        if (it + 1 < 32) {
            cp_stage(sm, 1 - (it & 1), it + 1, tid, i0, j0);
            CP_COMMIT();
            CP_WAIT(1);
        } else {
            CP_WAIT(0);
        }
        __syncthreads();

        const uint32_t* Sb = (const uint32_t*)(sm + (it & 1) * 8192);
        const uint32_t* Ah = Sb, *Al = Sb + 2048, *Bh = Sb + 4096, *Bl = Sb + 6144;
        #pragma unroll
        for (int ks = 0; ks < 2; ks++) {
            const int ca = ks * 8 + lm;
            uint32_t af[4][4], bh[4][2], bl[4][2];
            #pragma unroll
            for (int mt = 0; mt < 4; mt++) {
                int r = wm * 64 + mt * 16 + l4;
                af[mt][0] = Ah[adr(r, ca)];     af[mt][1] = Ah[adr(r + 8, ca)];
                af[mt][2] = Ah[adr(r, ca + 4)]; af[mt][3] = Ah[adr(r + 8, ca + 4)];
            }
            #pragma unroll
            for (int nt = 0; nt < 4; nt++) {
                int rn = wn * 32 + nt * 8 + l4;
                bh[nt][0] = Bh[adr(rn, ca)]; bh[nt][1] = Bh[adr(rn, ca + 4)];
                bl[nt][0] = Bl[adr(rn, ca)]; bl[nt][1] = Bl[adr(rn, ca + 4)];
            }
            #pragma unroll
            for (int mt = 0; mt < 4; mt++)
                #pragma unroll
                for (int nt = 0; nt < 4; nt++) mma8(acc[mt][nt], af[mt], bh[nt]);  // hi*hi
            #pragma unroll
            for (int mt = 0; mt < 4; mt++)
                #pragma unroll
                for (int nt = 0; nt < 4; nt++) mma8(acc[mt][nt], af[mt], bl[nt]);  // hi*lo
            #pragma unroll
            for (int mt = 0; mt < 4; mt++) {                                        // reuse af <- A_lo
                int r = wm * 64 + mt * 16 + l4;
                af[mt][0] = Al[adr(r, ca)];     af[mt][1] = Al[adr(r + 8, ca)];
                af[mt][2] = Al[adr(r, ca + 4)]; af[mt][3] = Al[adr(r + 8, ca + 4)];
            }
            #pragma unroll
            for (int mt = 0; mt < 4; mt++)
                #pragma unroll
                for (int nt = 0; nt < 4; nt++) mma8(acc[mt][nt], af[mt], bh[nt]);  // lo*hi
        }
        __syncthreads();
    }

    // epilogue: d2 = max(sqi+sqj-2*acc, 0) -> swizzled epi smem (aliases stages)
    float* epi = sm;
    #pragma unroll
    for (int mt = 0; mt < 4; mt++)
        #pragma unroll
        for (int nt = 0; nt < 4; nt++) {
            int r0 = wm * 64 + mt * 16 + l4;
            int c0 = wn * 32 + nt * 8 + lm * 2;
            #pragma unroll
            for (int i = 0; i < 4; i++) {
                int r = r0 + ((i >> 1) << 3);
                int c = c0 + (i & 1);
                float d = fmaxf(fmaf(-2.0f, acc[mt][nt][i], s_sqi[r] + s_sqj[c]), 0.0f);
                epi[r * 128 + ((c & ~31) | ((c ^ SWI(r)) & 31))] = d;
            }
        }
    __syncthreads();
    // normal tile
    for (int idx = tid; idx < 4096; idx += 256) {
        int r = idx >> 5, c4 = (idx & 31) << 2, sw = SWI(r);
        float4 o;
        o.x = epi[r * 128 + (((c4 + 0) & ~31) | (((c4 + 0) ^ sw) & 31))];
        o.y = epi[r * 128 + (((c4 + 1) & ~31) | (((c4 + 1) ^ sw) & 31))];
        o.z = epi[r * 128 + (((c4 + 2) & ~31) | (((c4 + 2) ^ sw) & 31))];
        o.w = epi[r * 128 + (((c4 + 3) & ~31) | (((c4 + 3) ^ sw) & 31))];
        *reinterpret_cast<float4*>(g_d2 + (size_t)(i0 + r) * N + j0 + c4) = o;
    }
    // transposed tile
    for (int idx = tid; idx < 4096; idx += 256) {
        int c = idx >> 5, r4 = (idx & 31) << 2;
        float4 o;
        o.x = epi[(r4 + 0) * 128 + ((c & ~31) | ((c ^ SWI(r4 + 0)) & 31))];
        o.y = epi[(r4 + 1) * 128 + ((c & ~31) | ((c ^ SWI(r4 + 1)) & 31))];
        o.z = epi[(r4 + 2) * 128 + ((c & ~31) | ((c ^ SWI(r4 + 2)) & 31))];
        o.w = epi[(r4 + 3) * 128 + ((c & ~31) | ((c ^ SWI(r4 + 3)) & 31))];
        *reinterpret_cast<float4*>(g_d2 + (size_t)(j0 + c) * N + i0 + r4) = o;
    }
}

// ---------------- select: exact 31st-smallest via 3-pass histogram ----------------
__global__ void __launch_bounds__(256) select_kernel() {
    const int row = blockIdx.x, tid = threadIdx.x;
    __shared__ unsigned bins[2048];
    __shared__ unsigned s_bin, s_below;

    unsigned u[16];
    {
        const float4* p = reinterpret_cast<const float4*>(g_d2 + (size_t)row * N);
        #pragma unroll
        for (int q = 0; q < 4; q++) {
            float4 f = p[tid + 256 * q];
            u[q * 4 + 0] = __float_as_uint(f.x); u[q * 4 + 1] = __float_as_uint(f.y);
            u[q * 4 + 2] = __float_as_uint(f.z); u[q * 4 + 3] = __float_as_uint(f.w);
        }
    }
    unsigned pref = 0, prefmask = 0, rank = KSEL;
    const int SH[3] = {20, 10, 0}, NB[3] = {2048, 1024, 1024};

    for (int p = 0; p < 3; p++) {
        const int sh = SH[p], nb = NB[p];
        for (int i = tid; i < nb; i += 256) bins[i] = 0;
        __syncthreads();
        #pragma unroll
        for (int q = 0; q < 16; q++)
            if ((u[q] & prefmask) == pref) atomicAdd(&bins[(u[q] >> sh) & (nb - 1)], 1);
        __syncthreads();
        if (tid < 32) {
            unsigned run = 0;
            for (int ch = 0; ch < nb / 32; ch++) {
                unsigned c = bins[ch * 32 + tid], s = c;
                #pragma unroll
                for (int o = 1; o < 32; o <<= 1) { unsigned x = __shfl_up_sync(0xffffffffu, s, o); if (tid >= o) s += x; }
                unsigned tot = __shfl_sync(0xffffffffu, s, 31);
                unsigned ball = __ballot_sync(0xffffffffu, run + s >= rank);
                if (ball) {
                    int l = __ffs(ball) - 1;
                    if (tid == l) { s_bin = ch * 32 + l; s_below = run + s - c; }
                    break;
                }
                run += tot;
            }
        }
        __syncthreads();
        pref |= s_bin << sh;
        prefmask |= (unsigned)(nb - 1) << sh;
        rank -= s_below;
        __syncthreads();
    }
    if (tid == 0) {
        float tv = __uint_as_float(pref);
        g_t[row] = tv;
        float scale = sqrtf(fmaxf(tv, 1e-12f));
        float denom = fmaxf(scale, 1e-8f);
        g_inv[row] = 1.0f / (denom * denom);
    }
}

// ---------------- output ----------------
__global__ void __launch_bounds__(256) out_kernel(float* __restrict__ outp) {
    size_t gid = (size_t)blockIdx.x * 256 + threadIdx.x;
    int row = (int)(gid >> 10), c0 = (int)(gid & 1023) << 2;
    float ti = g_t[row], invi = g_inv[row];
    float4 d  = *reinterpret_cast<const float4*>(g_d2 + (size_t)row * N + c0);
    float4 tj = *reinterpret_cast<const float4*>(g_t + c0);
    float4 ij = *reinterpret_cast<const float4*>(g_inv + c0);
    float4 o;
    o.x = 0.5f * ((d.x <= ti ? __expf(-d.x * invi) : 0.f) + (d.x <= tj.x ? __expf(-d.x * ij.x) : 0.f));
    o.y = 0.5f * ((d.y <= ti ? __expf(-d.y * invi) : 0.f) + (d.y <= tj.y ? __expf(-d.y * ij.y) : 0.f));
    o.z = 0.5f * ((d.z <= ti ? __expf(-d.z * invi) : 0.f) + (d.z <= tj.z ? __expf(-d.z * ij.z) : 0.f));
    o.w = 0.5f * ((d.w <= ti ? __expf(-d.w * invi) : 0.f) + (d.w <= tj.w ? __expf(-d.w * ij.w) : 0.f));
    *reinterpret_cast<float4*>(outp + (size_t)row * N + c0) = o;
}

// ---------------- launch ----------------
extern "C" void kernel_launch(void* const* d_in, const int* in_sizes, int n_in,
                              void* d_out, int out_size) {
    const float* X = (const float*)d_in[0];
    float* outp = (float*)d_out;
    const int smem = 16384 * 4;  // 64KB
    cudaFuncSetAttribute(gemm_kernel, cudaFuncAttributeMaxDynamicSharedMemorySize, smem);

    convert_kernel<<<(size_t)N * K / 4 / 256, 256>>>(X);
    norms_kernel<<<N, 128>>>(X);
    gemm_kernel<<<528, 256, smem>>>();
    select_kernel<<<N, 256>>>();
    out_kernel<<<(size_t)N * N / 4 / 256, 256>>>(outp);
}

// round 6
// speedup vs baseline: 2.8293x; 1.8990x over previous
#include <cuda_runtime.h>
#include <cuda_fp16.h>
#include <cstdint>

#define N 4096
#define K 512
#define KSEL 31

__device__ float  g_d2[(size_t)N * N];
__device__ float  g_sq[N];
__device__ float  g_t[N];
__device__ float  g_inv[N];
__device__ __half g_Xhi[(size_t)N * K];
__device__ __half g_Xlo[(size_t)N * K];

__device__ __forceinline__ uint32_t smem_u32(const void* p) {
    uint32_t a;
    asm("{ .reg .u64 t; cvta.to.shared.u64 t, %1; cvt.u32.u64 %0, t; }" : "=r"(a) : "l"(p));
    return a;
}
#define CP_COMMIT() asm volatile("cp.async.commit_group;" ::: "memory")
#define CP_WAIT(n)  asm volatile("cp.async.wait_group %0;" :: "n"(n) : "memory")

__device__ __forceinline__ void mma16(float* c, const uint32_t* a, const uint32_t* b) {
    asm("mma.sync.aligned.m16n8k16.row.col.f32.f16.f16.f32 "
        "{%0,%1,%2,%3}, {%4,%5,%6,%7}, {%8,%9}, {%0,%1,%2,%3};"
        : "+f"(c[0]), "+f"(c[1]), "+f"(c[2]), "+f"(c[3])
        : "r"(a[0]), "r"(a[1]), "r"(a[2]), "r"(a[3]), "r"(b[0]), "r"(b[1]));
}
#define LDSM4(r, addr) \
    asm volatile("ldmatrix.sync.aligned.m8n8.x4.shared.b16 {%0,%1,%2,%3}, [%4];" \
        : "=r"((r)[0]), "=r"((r)[1]), "=r"((r)[2]), "=r"((r)[3]) : "r"(addr))

#define SWI(i) ((((i) >> 2) + (((i) & 3) << 3)) & 31)
// smem row = 32 halves = 64B = 4 chunks of 16B; chunk xor-swizzled by (r>>1)&3
__device__ __forceinline__ uint32_t swz(int r, int c) {
    return (uint32_t)(r * 64 + ((c ^ ((r >> 1) & 3)) << 4));
}

// ---------------- convert: X -> fp16 hi + fp16 lo ----------------
__global__ void convert_kernel(const float* __restrict__ X) {
    size_t i = (size_t)blockIdx.x * 256 + threadIdx.x;
    float4 v = reinterpret_cast<const float4*>(X)[i];
    __half hx = __float2half_rn(v.x), hy = __float2half_rn(v.y);
    __half hz = __float2half_rn(v.z), hw = __float2half_rn(v.w);
    __half lx = __float2half_rn(v.x - __half2float(hx));
    __half ly = __float2half_rn(v.y - __half2float(hy));
    __half lz = __float2half_rn(v.z - __half2float(hz));
    __half lw = __float2half_rn(v.w - __half2float(hw));
    reinterpret_cast<__half2*>(g_Xhi)[i * 2 + 0] = __halves2half2(hx, hy);
    reinterpret_cast<__half2*>(g_Xhi)[i * 2 + 1] = __halves2half2(hz, hw);
    reinterpret_cast<__half2*>(g_Xlo)[i * 2 + 0] = __halves2half2(lx, ly);
    reinterpret_cast<__half2*>(g_Xlo)[i * 2 + 1] = __halves2half2(lz, lw);
}

// ---------------- norms (fp32 X) ----------------
__global__ void norms_kernel(const float* __restrict__ X) {
    int row = blockIdx.x, t = threadIdx.x;
    float4 v = reinterpret_cast<const float4*>(X + (size_t)row * K)[t];
    float s = v.x * v.x + v.y * v.y + v.z * v.z + v.w * v.w;
    #pragma unroll
    for (int o = 16; o; o >>= 1) s += __shfl_xor_sync(0xffffffffu, s, o);
    __shared__ float ws[4];
    if ((t & 31) == 0) ws[t >> 5] = s;
    __syncthreads();
    if (t == 0) g_sq[row] = ws[0] + ws[1] + ws[2] + ws[3];
}

// ---------------- GEMM via mma.sync fp16 (3-term split) ----------------
// stage = 4 bufs (Ahi,Alo,Bhi,Blo) x 128 rows x 32 halves = 32KB; 2 stages
#define STG 32768
#define BUF 8192

__device__ __forceinline__ void cp_stage(char* sm, int s, int it, int tid, int i0, int j0) {
    char* base = sm + s * STG;
    #pragma unroll
    for (int q = 0; q < 8; q++) {
        int idx = tid + 256 * q;
        int buf = idx >> 9, r = (idx >> 2) & 127, c = idx & 3;
        const __half* src = ((buf & 1) ? g_Xlo : g_Xhi)
                          + (size_t)(((buf < 2) ? i0 : j0) + r) * K + it * 32 + c * 8;
        uint32_t dst = smem_u32(base + buf * BUF) + swz(r, c);
        asm volatile("cp.async.cg.shared.global [%0], [%1], 16;" :: "r"(dst), "l"(src));
    }
}

__global__ void __launch_bounds__(256, 2) gemm_kernel() {
    __shared__ float s_sqi[128], s_sqj[128];
    extern __shared__ char sm[];                 // 64KB: 2 stages; epi aliases

    int t = blockIdx.x;                          // triangular tile -> (by,bx)
    int by = (int)(32.5f - sqrtf(32.5f * 32.5f - 2.0f * (float)t));
    while (by * (65 - by) / 2 > t) by--;
    while ((by + 1) * (64 - by) / 2 <= t) by++;
    int bx = by + (t - by * (65 - by) / 2);
    const int i0 = by * 128, j0 = bx * 128;

    const int tid = threadIdx.x;
    const int warp = tid >> 5, lane = tid & 31;
    const int wm = warp & 1, wn = warp >> 1;
    const int l4 = lane >> 2, lm = lane & 3;

    if (tid < 128) { s_sqi[tid] = g_sq[i0 + tid]; s_sqj[tid] = g_sq[j0 + tid]; }

    // ldmatrix per-thread address pieces
    const int rA = wm * 64 + (lane & 7) + ((lane >> 3) & 1) * 8;  // + mt*16
    const int cA = (lane >> 4) & 1;                               // + 2*ks
    const int rB = wn * 32 + (lane & 7) + ((lane >> 4) & 1) * 8;  // + p*16
    const int cB = (lane >> 3) & 1;                               // + 2*ks

    float acc[4][4][4];
    #pragma unroll
    for (int a = 0; a < 4; a++)
        #pragma unroll
        for (int b = 0; b < 4; b++)
            #pragma unroll
            for (int c = 0; c < 4; c++) acc[a][b][c] = 0.f;

    cp_stage(sm, 0, 0, tid, i0, j0);
    CP_COMMIT();

    for (int it = 0; it < 16; it++) {
        if (it + 1 < 16) { cp_stage(sm, 1 - (it & 1), it + 1, tid, i0, j0); CP_COMMIT(); CP_WAIT(1); }
        else CP_WAIT(0);
        __syncthreads();

        uint32_t Ah = smem_u32(sm + (it & 1) * STG);
        uint32_t Al = Ah + BUF, Bh = Ah + 2 * BUF, Bl = Ah + 3 * BUF;
        #pragma unroll
        for (int ks = 0; ks < 2; ks++) {
            uint32_t af[4][4], bh[4][2], bl[4][2];
            #pragma unroll
            for (int mt = 0; mt < 4; mt++) LDSM4(af[mt], Ah + swz(rA + mt * 16, cA + 2 * ks));
            #pragma unroll
            for (int p = 0; p < 2; p++) {
                uint32_t r4[4];
                LDSM4(r4, Bh + swz(rB + p * 16, cB + 2 * ks));
                bh[2 * p][0] = r4[0]; bh[2 * p][1] = r4[1];
                bh[2 * p + 1][0] = r4[2]; bh[2 * p + 1][1] = r4[3];
                LDSM4(r4, Bl + swz(rB + p * 16, cB + 2 * ks));
                bl[2 * p][0] = r4[0]; bl[2 * p][1] = r4[1];
                bl[2 * p + 1][0] = r4[2]; bl[2 * p + 1][1] = r4[3];
            }
            #pragma unroll
            for (int mt = 0; mt < 4; mt++)
                #pragma unroll
                for (int nt = 0; nt < 4; nt++) mma16(acc[mt][nt], af[mt], bh[nt]);   // hi*hi
            #pragma unroll
            for (int mt = 0; mt < 4; mt++)
                #pragma unroll
                for (int nt = 0; nt < 4; nt++) mma16(acc[mt][nt], af[mt], bl[nt]);   // hi*lo
            #pragma unroll
            for (int mt = 0; mt < 4; mt++) LDSM4(af[mt], Al + swz(rA + mt * 16, cA + 2 * ks));
            #pragma unroll
            for (int mt = 0; mt < 4; mt++)
                #pragma unroll
                for (int nt = 0; nt < 4; nt++) mma16(acc[mt][nt], af[mt], bh[nt]);   // lo*hi
        }
        __syncthreads();
    }

    // epilogue: d2 = max(sqi+sqj-2*acc, 0) -> swizzled epi smem (aliases stages)
    float* epi = reinterpret_cast<float*>(sm);
    #pragma unroll
    for (int mt = 0; mt < 4; mt++)
        #pragma unroll
        for (int nt = 0; nt < 4; nt++) {
            int r0 = wm * 64 + mt * 16 + l4;
            int c0 = wn * 32 + nt * 8 + lm * 2;
            #pragma unroll
            for (int i = 0; i < 4; i++) {
                int r = r0 + ((i >> 1) << 3);
                int c = c0 + (i & 1);
                float d = fmaxf(fmaf(-2.0f, acc[mt][nt][i], s_sqi[r] + s_sqj[c]), 0.0f);
                epi[r * 128 + ((c & ~31) | ((c ^ SWI(r)) & 31))] = d;
            }
        }
    __syncthreads();
    for (int idx = tid; idx < 4096; idx += 256) {
        int r = idx >> 5, c4 = (idx & 31) << 2, sw = SWI(r);
        float4 o;
        o.x = epi[r * 128 + (((c4 + 0) & ~31) | (((c4 + 0) ^ sw) & 31))];
        o.y = epi[r * 128 + (((c4 + 1) & ~31) | (((c4 + 1) ^ sw) & 31))];
        o.z = epi[r * 128 + (((c4 + 2) & ~31) | (((c4 + 2) ^ sw) & 31))];
        o.w = epi[r * 128 + (((c4 + 3) & ~31) | (((c4 + 3) ^ sw) & 31))];
        *reinterpret_cast<float4*>(g_d2 + (size_t)(i0 + r) * N + j0 + c4) = o;
    }
    for (int idx = tid; idx < 4096; idx += 256) {
        int c = idx >> 5, r4 = (idx & 31) << 2;
        float4 o;
        o.x = epi[(r4 + 0) * 128 + ((c & ~31) | ((c ^ SWI(r4 + 0)) & 31))];
        o.y = epi[(r4 + 1) * 128 + ((c & ~31) | ((c ^ SWI(r4 + 1)) & 31))];
        o.z = epi[(r4 + 2) * 128 + ((c & ~31) | ((c ^ SWI(r4 + 2)) & 31))];
        o.w = epi[(r4 + 3) * 128 + ((c & ~31) | ((c ^ SWI(r4 + 3)) & 31))];
        *reinterpret_cast<float4*>(g_d2 + (size_t)(j0 + c) * N + i0 + r4) = o;
    }
}

// ---------------- select: exact 31st-smallest, linear bins + candidate rank ----------------
__global__ void __launch_bounds__(256) select_kernel() {
    const int row = blockIdx.x, tid = threadIdx.x;
    const int warp = tid >> 5, lane = tid & 31;
    __shared__ unsigned bins[2048];
    __shared__ float cand[1024];
    __shared__ unsigned s_cnt, s_bin, s_below;
    __shared__ unsigned wsum[8];
    __shared__ float s_tv;

    float f[16];
    {
        const float4* p = reinterpret_cast<const float4*>(g_d2 + (size_t)row * N);
        #pragma unroll
        for (int q = 0; q < 4; q++) {
            float4 v = p[tid + 256 * q];
            f[q * 4 + 0] = v.x; f[q * 4 + 1] = v.y; f[q * 4 + 2] = v.z; f[q * 4 + 3] = v.w;
        }
    }
    #pragma unroll
    for (int i = 0; i < 8; i++) bins[tid + 256 * i] = 0;
    if (tid == 0) s_cnt = 0;
    __syncthreads();
    #pragma unroll
    for (int q = 0; q < 16; q++) atomicAdd(&bins[min((int)f[q], 2047)], 1u);
    __syncthreads();

    // block scan over 2048 bins (8 per thread)
    unsigned b8[8], loc = 0;
    #pragma unroll
    for (int i = 0; i < 8; i++) { b8[i] = bins[tid * 8 + i]; loc += b8[i]; }
    unsigned sc = loc;
    #pragma unroll
    for (int o = 1; o < 32; o <<= 1) { unsigned x = __shfl_up_sync(0xffffffffu, sc, o); if (lane >= o) sc += x; }
    if (lane == 31) wsum[warp] = sc;
    __syncthreads();
    if (tid == 0) { unsigned a = 0; for (int w = 0; w < 8; w++) { unsigned x = wsum[w]; wsum[w] = a; a += x; } }
    __syncthreads();
    unsigned before = wsum[warp] + sc - loc;       // exclusive prefix of this thread's chunk
    if (before < KSEL && before + loc >= KSEL) {
        unsigned cum = before;
        #pragma unroll
        for (int i = 0; i < 8; i++) {
            if (cum + b8[i] >= KSEL) { s_bin = tid * 8 + i; s_below = cum; break; }
            cum += b8[i];
        }
    }
    __syncthreads();
    const unsigned b = s_bin, rp = KSEL - s_below; // rank within bin, 1-based
    #pragma unroll
    for (int q = 0; q < 16; q++)
        if ((unsigned)min((int)f[q], 2047) == b) {
            unsigned id = atomicAdd(&s_cnt, 1u);
            if (id < 1024) cand[id] = f[q];
        }
    __syncthreads();
    const unsigned c = min(s_cnt, 1024u);
    for (unsigned i = tid; i < c; i += 256) {
        float v = cand[i];
        unsigned less = 0, eq = 0;
        for (unsigned j = 0; j < c; j++) { float w = cand[j]; less += (w < v); eq += (w == v); }
        if (less < rp && less + eq >= rp) s_tv = v;
    }
    __syncthreads();
    if (tid == 0) {
        float tv = s_tv;
        g_t[row] = tv;
        float scale = sqrtf(fmaxf(tv, 1e-12f));
        float denom = fmaxf(scale, 1e-8f);
        g_inv[row] = 1.0f / (denom * denom);
    }
}

// ---------------- output ----------------
__global__ void __launch_bounds__(256) out_kernel(float* __restrict__ outp) {
    size_t gid = (size_t)blockIdx.x * 256 + threadIdx.x;
    int row = (int)(gid >> 10), c0 = (int)(gid & 1023) << 2;
    float ti = g_t[row], invi = g_inv[row];
    float4 d  = *reinterpret_cast<const float4*>(g_d2 + (size_t)row * N + c0);
    float4 tj = *reinterpret_cast<const float4*>(g_t + c0);
    float4 ij = *reinterpret_cast<const float4*>(g_inv + c0);
    float4 o;
    o.x = 0.5f * ((d.x <= ti ? __expf(-d.x * invi) : 0.f) + (d.x <= tj.x ? __expf(-d.x * ij.x) : 0.f));
    o.y = 0.5f * ((d.y <= ti ? __expf(-d.y * invi) : 0.f) + (d.y <= tj.y ? __expf(-d.y * ij.y) : 0.f));
    o.z = 0.5f * ((d.z <= ti ? __expf(-d.z * invi) : 0.f) + (d.z <= tj.z ? __expf(-d.z * ij.z) : 0.f));
    o.w = 0.5f * ((d.w <= ti ? __expf(-d.w * invi) : 0.f) + (d.w <= tj.w ? __expf(-d.w * ij.w) : 0.f));
    *reinterpret_cast<float4*>(outp + (size_t)row * N + c0) = o;
}

// ---------------- launch ----------------
extern "C" void kernel_launch(void* const* d_in, const int* in_sizes, int n_in,
                              void* d_out, int out_size) {
    const float* X = (const float*)d_in[0];
    float* outp = (float*)d_out;
    const int smem = 2 * STG;    // 64KB
    cudaFuncSetAttribute(gemm_kernel, cudaFuncAttributeMaxDynamicSharedMemorySize, smem);

    convert_kernel<<<(size_t)N * K / 4 / 256, 256>>>(X);
    norms_kernel<<<N, 128>>>(X);
    gemm_kernel<<<528, 256, smem>>>();
    select_kernel<<<N, 256>>>();
    out_kernel<<<(size_t)N * N / 4 / 256, 256>>>(outp);
}